// round 2
// baseline (speedup 1.0000x reference)
#include <cuda_runtime.h>

// ---------------------------------------------------------------------------
// ReservoirLinearRNN: only the LAST timestep of the scan feeds the output.
// h_last = sum_{k<K} Bu[T-1-k] A^k  (K=256 truncation; ||A^k||=0.95^k, err~1e-5)
// Factor k = 16c + r:  h = sum_c ( sum_r Bu_rev[16c+r] P_r ) R_c
//   P_r = A^r (r<16) at g_PR slots 0..15
//   R_c = (A^16)^c  (c=1..15) at slots 16..30  (R1 computed in the P9..P15
//   batch since R1 = P8@P8; the R_0 = I term is folded into the epilogue).
// ---------------------------------------------------------------------------

namespace {
constexpr int HN   = 512;
constexpr int TT   = 2048;
constexpr int BB   = 16;
constexpr int LL   = 128;
constexpr int MMc  = 256;
constexpr int FF   = 1024;
constexpr int MSZ  = HN * HN;     // 262144 floats per 512x512 matrix
constexpr int ROFF = 16 * MSZ;    // R1 lives here (slot 16)
}

// Scratch (device globals: allowed; no allocations permitted)
__device__ float g_Weff[LL * HN];          // We @ Wb  (128 x 512)
__device__ float g_beff[HN];               // be @ Wb
__device__ float g_BuR[4096 * HN];         // rows m = c*256+b*16+r  (4096 x 512)
__device__ float g_PR[31 * MSZ];           // P[0..15] then R[1..15]
__device__ float g_Spart[8 * 256 * HN];    // split-K partials for S
__device__ float g_S[BB * 16 * HN];        // (b, c*512+j)
__device__ float g_Hpart[15 * BB * HN];    // split-K partials for h (c=1..15)
__device__ float g_zn[BB * HN];
__device__ float g_t1[BB * FF];

// --------------------------- init: Weff, beff, P0=I, P1=A -------------------
__global__ void k_init(const float* __restrict__ We, const float* __restrict__ be,
                       const float* __restrict__ Wb, const float* __restrict__ A) {
    const int nWeff = LL * HN;                 // 65536
    const int total = nWeff + HN + 2 * MSZ;
    for (int id = blockIdx.x * blockDim.x + threadIdx.x; id < total;
         id += gridDim.x * blockDim.x) {
        if (id < nWeff) {
            int l = id / HN, h = id % HN;
            float acc = 0.f;
            for (int m = 0; m < MMc; m++) acc += We[l * MMc + m] * Wb[m * HN + h];
            g_Weff[id] = acc;
        } else if (id < nWeff + HN) {
            int h = id - nWeff;
            float acc = 0.f;
            for (int m = 0; m < MMc; m++) acc += be[m] * Wb[m * HN + h];
            g_beff[h] = acc;
        } else if (id < nWeff + HN + MSZ) {
            int i = id - (nWeff + HN);
            g_PR[i] = (i / HN == i % HN) ? 1.f : 0.f;            // P0 = I
        } else {
            int i = id - (nWeff + HN + MSZ);
            g_PR[MSZ + i] = A[i];                                // P1 = A
        }
    }
}

// --------------------------- Bu window GEMM ---------------------------------
// C(4096,512) row m=c*256+b*16+r : x[b, 2047-(16c+r), :] @ Weff + beff
__global__ __launch_bounds__(256) void k_bu(const float* __restrict__ x) {
    __shared__ float As[32][64];   // [k][m]
    __shared__ float Bs[32][64];   // [k][n]
    int t  = threadIdx.x;
    int m0 = blockIdx.x * 64, n0 = blockIdx.y * 64;
    int r  = t >> 2, c0 = (t & 3) * 8;
    int m  = m0 + r;
    int cc = m >> 8, b = (m >> 4) & 15, rr = m & 15;
    int tt = (TT - 1) - (cc * 16 + rr);
    const float* xrow = x + ((size_t)(b * TT + tt)) * LL;
    int rb = t >> 3, cb = (t & 7) * 8;
    int tx = t & 15, ty = t >> 4;
    float acc[4][4] = {};
    for (int k0 = 0; k0 < LL; k0 += 32) {
        float4 v0 = *(const float4*)(xrow + k0 + c0);
        float4 v1 = *(const float4*)(xrow + k0 + c0 + 4);
        As[c0 + 0][r] = v0.x; As[c0 + 1][r] = v0.y; As[c0 + 2][r] = v0.z; As[c0 + 3][r] = v0.w;
        As[c0 + 4][r] = v1.x; As[c0 + 5][r] = v1.y; As[c0 + 6][r] = v1.z; As[c0 + 7][r] = v1.w;
        const float* bp = g_Weff + (size_t)(k0 + rb) * HN + n0 + cb;
        *(float4*)&Bs[rb][cb]     = *(const float4*)bp;
        *(float4*)&Bs[rb][cb + 4] = *(const float4*)(bp + 4);
        __syncthreads();
#pragma unroll
        for (int kk = 0; kk < 32; kk++) {
            float4 a4 = *(const float4*)&As[kk][ty * 4];
            float4 b4 = *(const float4*)&Bs[kk][tx * 4];
            acc[0][0] += a4.x * b4.x; acc[0][1] += a4.x * b4.y; acc[0][2] += a4.x * b4.z; acc[0][3] += a4.x * b4.w;
            acc[1][0] += a4.y * b4.x; acc[1][1] += a4.y * b4.y; acc[1][2] += a4.y * b4.z; acc[1][3] += a4.y * b4.w;
            acc[2][0] += a4.z * b4.x; acc[2][1] += a4.z * b4.y; acc[2][2] += a4.z * b4.z; acc[2][3] += a4.z * b4.w;
            acc[3][0] += a4.w * b4.x; acc[3][1] += a4.w * b4.y; acc[3][2] += a4.w * b4.z; acc[3][3] += a4.w * b4.w;
        }
        __syncthreads();
    }
#pragma unroll
    for (int i = 0; i < 4; i++) {
        int col = n0 + tx * 4;
        float4 v;
        v.x = acc[i][0] + g_beff[col + 0];
        v.y = acc[i][1] + g_beff[col + 1];
        v.z = acc[i][2] + g_beff[col + 2];
        v.w = acc[i][3] + g_beff[col + 3];
        *(float4*)&g_BuR[(size_t)(m0 + ty * 4 + i) * HN + col] = v;
    }
}

// --------------------------- batched 512x512x512 GEMM -----------------------
// C[z] = A @ B[z]; all operands live inside g_PR at float offsets.
__global__ __launch_bounds__(256) void k_mm512(long aoff, long boff, long coff) {
    const float* Ap = g_PR + aoff;
    const float* Bz = g_PR + boff + (long)blockIdx.z * MSZ;
    float*       Cz = g_PR + coff + (long)blockIdx.z * MSZ;
    __shared__ float As[32][64];
    __shared__ float Bs[32][64];
    int t  = threadIdx.x;
    int m0 = blockIdx.x * 64, n0 = blockIdx.y * 64;
    int r  = t >> 2, c0 = (t & 3) * 8;
    int rb = t >> 3, cb = (t & 7) * 8;
    int tx = t & 15, ty = t >> 4;
    float acc[4][4] = {};
    for (int k0 = 0; k0 < HN; k0 += 32) {
        const float* ap = Ap + (size_t)(m0 + r) * HN + k0 + c0;
        float4 v0 = *(const float4*)ap;
        float4 v1 = *(const float4*)(ap + 4);
        As[c0 + 0][r] = v0.x; As[c0 + 1][r] = v0.y; As[c0 + 2][r] = v0.z; As[c0 + 3][r] = v0.w;
        As[c0 + 4][r] = v1.x; As[c0 + 5][r] = v1.y; As[c0 + 6][r] = v1.z; As[c0 + 7][r] = v1.w;
        const float* bp = Bz + (size_t)(k0 + rb) * HN + n0 + cb;
        *(float4*)&Bs[rb][cb]     = *(const float4*)bp;
        *(float4*)&Bs[rb][cb + 4] = *(const float4*)(bp + 4);
        __syncthreads();
#pragma unroll
        for (int kk = 0; kk < 32; kk++) {
            float4 a4 = *(const float4*)&As[kk][ty * 4];
            float4 b4 = *(const float4*)&Bs[kk][tx * 4];
            acc[0][0] += a4.x * b4.x; acc[0][1] += a4.x * b4.y; acc[0][2] += a4.x * b4.z; acc[0][3] += a4.x * b4.w;
            acc[1][0] += a4.y * b4.x; acc[1][1] += a4.y * b4.y; acc[1][2] += a4.y * b4.z; acc[1][3] += a4.y * b4.w;
            acc[2][0] += a4.z * b4.x; acc[2][1] += a4.z * b4.y; acc[2][2] += a4.z * b4.z; acc[2][3] += a4.z * b4.w;
            acc[3][0] += a4.w * b4.x; acc[3][1] += a4.w * b4.y; acc[3][2] += a4.w * b4.z; acc[3][3] += a4.w * b4.w;
        }
        __syncthreads();
    }
#pragma unroll
    for (int i = 0; i < 4; i++) {
        float4 v = {acc[i][0], acc[i][1], acc[i][2], acc[i][3]};
        *(float4*)&Cz[(size_t)(m0 + ty * 4 + i) * HN + n0 + tx * 4] = v;
    }
}

// --------------------------- S = BuR(256,8192) @ Pstack(8192,512), split-K --
__global__ __launch_bounds__(256) void k_s_split() {
    __shared__ float As[32][64];
    __shared__ float Bs[32][64];
    int t  = threadIdx.x;
    int m0 = blockIdx.x * 64, n0 = blockIdx.y * 64;
    int kb = blockIdx.z * 1024;
    int r  = t >> 2, c0 = (t & 3) * 8;
    int rb = t >> 3, cb = (t & 7) * 8;
    int tx = t & 15, ty = t >> 4;
    float acc[4][4] = {};
    for (int k0 = kb; k0 < kb + 1024; k0 += 32) {
        const float* ap = g_BuR + (size_t)(m0 + r) * 8192 + k0 + c0;
        float4 v0 = *(const float4*)ap;
        float4 v1 = *(const float4*)(ap + 4);
        As[c0 + 0][r] = v0.x; As[c0 + 1][r] = v0.y; As[c0 + 2][r] = v0.z; As[c0 + 3][r] = v0.w;
        As[c0 + 4][r] = v1.x; As[c0 + 5][r] = v1.y; As[c0 + 6][r] = v1.z; As[c0 + 7][r] = v1.w;
        const float* bp = g_PR + (size_t)(k0 + rb) * HN + n0 + cb;   // Pstack (P0..P15)
        *(float4*)&Bs[rb][cb]     = *(const float4*)bp;
        *(float4*)&Bs[rb][cb + 4] = *(const float4*)(bp + 4);
        __syncthreads();
#pragma unroll
        for (int kk = 0; kk < 32; kk++) {
            float4 a4 = *(const float4*)&As[kk][ty * 4];
            float4 b4 = *(const float4*)&Bs[kk][tx * 4];
            acc[0][0] += a4.x * b4.x; acc[0][1] += a4.x * b4.y; acc[0][2] += a4.x * b4.z; acc[0][3] += a4.x * b4.w;
            acc[1][0] += a4.y * b4.x; acc[1][1] += a4.y * b4.y; acc[1][2] += a4.y * b4.z; acc[1][3] += a4.y * b4.w;
            acc[2][0] += a4.z * b4.x; acc[2][1] += a4.z * b4.y; acc[2][2] += a4.z * b4.z; acc[2][3] += a4.z * b4.w;
            acc[3][0] += a4.w * b4.x; acc[3][1] += a4.w * b4.y; acc[3][2] += a4.w * b4.z; acc[3][3] += a4.w * b4.w;
        }
        __syncthreads();
    }
    float* outp = g_Spart + (size_t)blockIdx.z * 131072;
#pragma unroll
    for (int i = 0; i < 4; i++) {
        float4 v = {acc[i][0], acc[i][1], acc[i][2], acc[i][3]};
        *(float4*)&outp[(size_t)(m0 + ty * 4 + i) * HN + n0 + tx * 4] = v;
    }
}

// reduce split-K partials; transpose rows m=c*16+b -> S[b][c*512+j]
__global__ void k_s_reduce() {
    int mm = blockIdx.x, j = threadIdx.x;
    float a = 0.f;
#pragma unroll
    for (int s = 0; s < 8; s++) a += g_Spart[(size_t)s * 131072 + (size_t)mm * HN + j];
    int b = mm & 15, c = mm >> 4;
    g_S[(size_t)b * 8192 + c * HN + j] = a;
}

// --------------------------- h = S(16,c=1..15) @ Rstack(7680,512), split-K --
__global__ __launch_bounds__(256) void k_h_split() {
    __shared__ float As[16][32];
    __shared__ float Bs[32][64];
    int t   = threadIdx.x;
    int n0  = blockIdx.x * 64;
    int kb  = blockIdx.y * 512;          // blockIdx.y in [0,15): k = (c-1)*512 + l
    int col = t & 63, rq = t >> 6;
    float acc[4] = {};
    for (int k0 = kb; k0 < kb + 512; k0 += 32) {
        {
            // S column offset: skip the c=0 block (handled in k_ln)
            int ar = t >> 5, ac = t & 31;
            As[ar][ac] = g_S[(size_t)ar * 8192 + 512 + k0 + ac];
            int t2 = t + 256, ar2 = t2 >> 5, ac2 = t2 & 31;
            As[ar2][ac2] = g_S[(size_t)ar2 * 8192 + 512 + k0 + ac2];
        }
        int rb = t >> 3, cb = (t & 7) * 8;
        const float* bp = g_PR + ROFF + (size_t)(k0 + rb) * HN + n0 + cb;  // R1..R15
        *(float4*)&Bs[rb][cb]     = *(const float4*)bp;
        *(float4*)&Bs[rb][cb + 4] = *(const float4*)(bp + 4);
        __syncthreads();
#pragma unroll
        for (int kk = 0; kk < 32; kk++) {
            float bv = Bs[kk][col];
            acc[0] += As[rq][kk] * bv;
            acc[1] += As[rq + 4][kk] * bv;
            acc[2] += As[rq + 8][kk] * bv;
            acc[3] += As[rq + 12][kk] * bv;
        }
        __syncthreads();
    }
#pragma unroll
    for (int q = 0; q < 4; q++)
        g_Hpart[(size_t)blockIdx.y * 8192 + (size_t)(rq + q * 4) * HN + n0 + col] = acc[q];
}

// --------------------------- z_last + layernorm -----------------------------
__global__ void k_ln(const float* __restrict__ x, const float* __restrict__ Wr,
                     const float* __restrict__ br, const float* __restrict__ lg,
                     const float* __restrict__ lb) {
    int b = blockIdx.x, j = threadIdx.x;    // 512 threads
    __shared__ float xs[LL];
    __shared__ float red[HN];
    if (j < LL) xs[j] = x[(size_t)(b * TT + (TT - 1)) * LL + j];
    __syncthreads();
    float hv = g_S[(size_t)b * 8192 + j];   // c = 0 term (R0 = I)
#pragma unroll
    for (int s = 0; s < 15; s++) hv += g_Hpart[(size_t)s * 8192 + (size_t)b * HN + j];
    float acc = br[j];
#pragma unroll 8
    for (int l = 0; l < LL; l++) acc += xs[l] * Wr[(size_t)l * HN + j];
    float z = hv + acc;
    red[j] = z; __syncthreads();
    for (int off = 256; off > 0; off >>= 1) {
        if (j < off) red[j] += red[j + off];
        __syncthreads();
    }
    float mu = red[0] / (float)HN;
    __syncthreads();
    float d = z - mu;
    red[j] = d * d; __syncthreads();
    for (int off = 256; off > 0; off >>= 1) {
        if (j < off) red[j] += red[j + off];
        __syncthreads();
    }
    float var = red[0] / (float)HN;
    g_zn[(size_t)b * HN + j] = d * rsqrtf(var + 1e-5f) * lg[j] + lb[j];
}

// --------------------------- MLP ---------------------------------------------
__global__ void k_mlp1(const float* __restrict__ W1, const float* __restrict__ b1) {
    int b = blockIdx.x;
    int f = blockIdx.y * 128 + threadIdx.x;
    __shared__ float zs[HN];
    for (int i = threadIdx.x; i < HN; i += 128) zs[i] = g_zn[(size_t)b * HN + i];
    __syncthreads();
    float acc = b1[f];
#pragma unroll 8
    for (int j = 0; j < HN; j++) acc += zs[j] * W1[(size_t)j * FF + f];
    g_t1[(size_t)b * FF + f] = fmaxf(acc, 0.f);
}

__global__ void k_mlp2(const float* __restrict__ W2, const float* __restrict__ b2,
                       float* __restrict__ out) {
    int b = blockIdx.x;
    int j = blockIdx.y * 128 + threadIdx.x;
    __shared__ float ts[FF];
    for (int i = threadIdx.x; i < FF; i += 128) ts[i] = g_t1[(size_t)b * FF + i];
    __syncthreads();
    float acc = b2[j];
#pragma unroll 8
    for (int f = 0; f < FF; f++) acc += ts[f] * W2[(size_t)f * HN + j];
    out[(size_t)b * HN + j] = acc;
}

// --------------------------- launch -----------------------------------------
extern "C" void kernel_launch(void* const* d_in, const int* in_sizes, int n_in,
                              void* d_out, int out_size) {
    const float* x  = (const float*)d_in[0];
    const float* We = (const float*)d_in[1];
    const float* be = (const float*)d_in[2];
    const float* Wb = (const float*)d_in[3];
    const float* A  = (const float*)d_in[4];
    const float* Wr = (const float*)d_in[5];
    const float* br = (const float*)d_in[6];
    const float* lg = (const float*)d_in[7];
    const float* lb = (const float*)d_in[8];
    const float* W1 = (const float*)d_in[9];
    const float* b1 = (const float*)d_in[10];
    const float* W2 = (const float*)d_in[11];
    const float* b2 = (const float*)d_in[12];
    float* out = (float*)d_out;

    k_init<<<1024, 256>>>(We, be, Wb, A);
    k_bu<<<dim3(64, 8), 256>>>(x);

    // P chain: P0=I, P1=A already set.  P[m+s] = P[m] @ P[s]
    k_mm512<<<dim3(8, 8, 1), 256>>>(1L * MSZ, 1L * MSZ, 2L * MSZ);   // P2
    k_mm512<<<dim3(8, 8, 2), 256>>>(2L * MSZ, 1L * MSZ, 3L * MSZ);   // P3,P4
    k_mm512<<<dim3(8, 8, 4), 256>>>(4L * MSZ, 1L * MSZ, 5L * MSZ);   // P5..P8
    // P9..P15 AND R1: z=0..6 -> P8@P1..P7 -> P9..P15 ; z=7 -> P8@P8 -> slot16 = R1
    k_mm512<<<dim3(8, 8, 8), 256>>>(8L * MSZ, 1L * MSZ, 9L * MSZ);
    // R chain (R_c at slot 15+c): doubling off R1
    k_mm512<<<dim3(8, 8, 1), 256>>>(16L * MSZ, 16L * MSZ, 17L * MSZ); // R2
    k_mm512<<<dim3(8, 8, 2), 256>>>(17L * MSZ, 16L * MSZ, 18L * MSZ); // R3,R4
    k_mm512<<<dim3(8, 8, 4), 256>>>(19L * MSZ, 16L * MSZ, 20L * MSZ); // R5..R8
    k_mm512<<<dim3(8, 8, 7), 256>>>(23L * MSZ, 16L * MSZ, 24L * MSZ); // R9..R15

    k_s_split<<<dim3(4, 8, 8), 256>>>();
    k_s_reduce<<<256, 512>>>();
    k_h_split<<<dim3(8, 15), 256>>>();
    k_ln<<<16, 512>>>(x, Wr, br, lg, lb);
    k_mlp1<<<dim3(16, 8), 128>>>(W1, b1);
    k_mlp2<<<dim3(16, 4), 128>>>(W2, b2, out);
}

// round 3
// speedup vs baseline: 1.4081x; 1.4081x over previous
#include <cuda_runtime.h>

// ---------------------------------------------------------------------------
// ReservoirLinearRNN — only the LAST timestep feeds the output.
// h_last = sum_{k<256} U_k A^k   (K=256 truncation, ||A^k||=0.95^k, err ~1e-6)
// Binary combine tree: V_{l+1}[j] = V_l[2j] + V_l[2j+1] @ M_l,  M_l = A^(2^l).
// Only 7 squarings needed (A^2..A^128) instead of 29 full products.
// All 512x512 GEMMs are K-split (z=2) writing partial halves; consumers sum
// the two halves at load time (no reduction launches).
// ---------------------------------------------------------------------------

namespace {
constexpr int HN  = 512;
constexpr int TT  = 2048;
constexpr int LL  = 128;
constexpr int MMc = 256;
constexpr int FF  = 1024;
constexpr int MSZ = HN * HN;      // 262144 floats
}

// Scratch (device globals only — no allocations)
__device__ float g_Weff[LL * HN];
__device__ float g_beff[HN];
__device__ float g_Va[4096 * HN];          // V0: rows m = k*16 + b (k = lag)
__device__ float g_V1[2 * 2048 * HN];      // ping (holds up to 2048 rows x 2 halves)
__device__ float g_V2[2 * 1024 * HN];      // pong (holds up to 1024 rows x 2 halves)
__device__ float g_M[7 * 2 * MSZ];         // M1..M7, each as 2 K-split halves
__device__ float g_zn[16 * HN];
__device__ float g_t1[16 * FF];

// --------------------------- init: Weff = We@Wb, beff = be@Wb ---------------
__global__ void k_init(const float* __restrict__ We, const float* __restrict__ be,
                       const float* __restrict__ Wb) {
    const int nWeff = LL * HN;
    const int total = nWeff + HN;
    for (int id = blockIdx.x * blockDim.x + threadIdx.x; id < total;
         id += gridDim.x * blockDim.x) {
        if (id < nWeff) {
            int l = id / HN, h = id % HN;
            float acc = 0.f;
            for (int m = 0; m < MMc; m++) acc += We[l * MMc + m] * Wb[m * HN + h];
            g_Weff[id] = acc;
        } else {
            int h = id - nWeff;
            float acc = 0.f;
            for (int m = 0; m < MMc; m++) acc += be[m] * Wb[m * HN + h];
            g_beff[h] = acc;
        }
    }
}

// --------------------------- V0 = Bu window GEMM -----------------------------
// row m = k*16 + b  ->  x[b, 2047-k, :] @ Weff + beff     (4096 x 512)
__global__ __launch_bounds__(256) void k_bu(const float* __restrict__ x) {
    __shared__ float As[32][64];   // [k][m]
    __shared__ float Bs[32][64];   // [k][n]
    int t  = threadIdx.x;
    int m0 = blockIdx.x * 64, n0 = blockIdx.y * 64;
    int r  = t >> 2, c0 = (t & 3) * 8;
    int m  = m0 + r;
    int k  = m >> 4, b = m & 15;
    int tt = (TT - 1) - k;
    const float* xrow = x + ((size_t)(b * TT + tt)) * LL;
    int rb = t >> 3, cb = (t & 7) * 8;
    int tx = t & 15, ty = t >> 4;
    float acc[4][4] = {};
    for (int k0 = 0; k0 < LL; k0 += 32) {
        float4 v0 = *(const float4*)(xrow + k0 + c0);
        float4 v1 = *(const float4*)(xrow + k0 + c0 + 4);
        As[c0 + 0][r] = v0.x; As[c0 + 1][r] = v0.y; As[c0 + 2][r] = v0.z; As[c0 + 3][r] = v0.w;
        As[c0 + 4][r] = v1.x; As[c0 + 5][r] = v1.y; As[c0 + 6][r] = v1.z; As[c0 + 7][r] = v1.w;
        const float* bp = g_Weff + (size_t)(k0 + rb) * HN + n0 + cb;
        *(float4*)&Bs[rb][cb]     = *(const float4*)bp;
        *(float4*)&Bs[rb][cb + 4] = *(const float4*)(bp + 4);
        __syncthreads();
#pragma unroll
        for (int kk = 0; kk < 32; kk++) {
            float4 a4 = *(const float4*)&As[kk][ty * 4];
            float4 b4 = *(const float4*)&Bs[kk][tx * 4];
            acc[0][0] += a4.x * b4.x; acc[0][1] += a4.x * b4.y; acc[0][2] += a4.x * b4.z; acc[0][3] += a4.x * b4.w;
            acc[1][0] += a4.y * b4.x; acc[1][1] += a4.y * b4.y; acc[1][2] += a4.y * b4.z; acc[1][3] += a4.y * b4.w;
            acc[2][0] += a4.z * b4.x; acc[2][1] += a4.z * b4.y; acc[2][2] += a4.z * b4.z; acc[2][3] += a4.z * b4.w;
            acc[3][0] += a4.w * b4.x; acc[3][1] += a4.w * b4.y; acc[3][2] += a4.w * b4.z; acc[3][3] += a4.w * b4.w;
        }
        __syncthreads();
    }
#pragma unroll
    for (int i = 0; i < 4; i++) {
        int col = n0 + tx * 4;
        float4 v;
        v.x = acc[i][0] + g_beff[col + 0];
        v.y = acc[i][1] + g_beff[col + 1];
        v.z = acc[i][2] + g_beff[col + 2];
        v.w = acc[i][3] + g_beff[col + 3];
        *(float4*)&g_Va[(size_t)(m0 + ty * 4 + i) * HN + col] = v;
    }
}

// --------------------------- squaring: C = (a0+a1) @ (b0+b1) ----------------
// grid (8,8,2): z = K-half; writes partial half z at cOut + z*MSZ.
__global__ __launch_bounds__(256) void k_sq(const float* __restrict__ a0,
                                            const float* __restrict__ a1,
                                            const float* __restrict__ b0,
                                            const float* __restrict__ b1,
                                            float* __restrict__ cOut) {
    __shared__ float As[32][64];
    __shared__ float Bs[32][64];
    int t  = threadIdx.x;
    int m0 = blockIdx.x * 64, n0 = blockIdx.y * 64;
    int kbeg = blockIdx.z * 256;
    int r  = t >> 2, c0 = (t & 3) * 8;
    int rb = t >> 3, cb = (t & 7) * 8;
    int tx = t & 15, ty = t >> 4;
    float acc[4][4] = {};
    for (int k0 = kbeg; k0 < kbeg + 256; k0 += 32) {
        size_t aoff = (size_t)(m0 + r) * HN + k0 + c0;
        float4 v0 = *(const float4*)(a0 + aoff);
        float4 v1 = *(const float4*)(a0 + aoff + 4);
        if (a1) {
            float4 w0 = *(const float4*)(a1 + aoff);
            float4 w1 = *(const float4*)(a1 + aoff + 4);
            v0.x += w0.x; v0.y += w0.y; v0.z += w0.z; v0.w += w0.w;
            v1.x += w1.x; v1.y += w1.y; v1.z += w1.z; v1.w += w1.w;
        }
        As[c0 + 0][r] = v0.x; As[c0 + 1][r] = v0.y; As[c0 + 2][r] = v0.z; As[c0 + 3][r] = v0.w;
        As[c0 + 4][r] = v1.x; As[c0 + 5][r] = v1.y; As[c0 + 6][r] = v1.z; As[c0 + 7][r] = v1.w;
        size_t boff = (size_t)(k0 + rb) * HN + n0 + cb;
        float4 u0 = *(const float4*)(b0 + boff);
        float4 u1 = *(const float4*)(b0 + boff + 4);
        if (b1) {
            float4 w0 = *(const float4*)(b1 + boff);
            float4 w1 = *(const float4*)(b1 + boff + 4);
            u0.x += w0.x; u0.y += w0.y; u0.z += w0.z; u0.w += w0.w;
            u1.x += w1.x; u1.y += w1.y; u1.z += w1.z; u1.w += w1.w;
        }
        *(float4*)&Bs[rb][cb]     = u0;
        *(float4*)&Bs[rb][cb + 4] = u1;
        __syncthreads();
#pragma unroll
        for (int kk = 0; kk < 32; kk++) {
            float4 a4 = *(const float4*)&As[kk][ty * 4];
            float4 b4 = *(const float4*)&Bs[kk][tx * 4];
            acc[0][0] += a4.x * b4.x; acc[0][1] += a4.x * b4.y; acc[0][2] += a4.x * b4.z; acc[0][3] += a4.x * b4.w;
            acc[1][0] += a4.y * b4.x; acc[1][1] += a4.y * b4.y; acc[1][2] += a4.y * b4.z; acc[1][3] += a4.y * b4.w;
            acc[2][0] += a4.z * b4.x; acc[2][1] += a4.z * b4.y; acc[2][2] += a4.z * b4.z; acc[2][3] += a4.z * b4.w;
            acc[3][0] += a4.w * b4.x; acc[3][1] += a4.w * b4.y; acc[3][2] += a4.w * b4.z; acc[3][3] += a4.w * b4.w;
        }
        __syncthreads();
    }
    float* cz = cOut + (size_t)blockIdx.z * MSZ;
#pragma unroll
    for (int i = 0; i < 4; i++) {
        float4 v = {acc[i][0], acc[i][1], acc[i][2], acc[i][3]};
        *(float4*)&cz[(size_t)(m0 + ty * 4 + i) * HN + n0 + tx * 4] = v;
    }
}

// --------------------------- tree combine -----------------------------------
// out[j] = V[2j] + V[2j+1] @ (M half0 + half1)
// vin rows = 2*rows_out, row = k*16+b.  vhoff = element offset of vin half1
// (0 => vin is single-precision full values, no halves).
// grid (ceil(rows_out/64), 8, 2): z = K-half; out half z at vout + z*rows_out*HN.
__global__ __launch_bounds__(256) void k_vec(const float* __restrict__ vin, int vhoff,
                                             const float* __restrict__ b0,
                                             const float* __restrict__ b1,
                                             float* __restrict__ vout, int rows_out) {
    __shared__ float As[32][64];
    __shared__ float Bs[32][64];
    int t  = threadIdx.x;
    int m0 = blockIdx.x * 64, n0 = blockIdx.y * 64;
    int kbeg = blockIdx.z * 256;
    int r  = t >> 2, c0 = (t & 3) * 8;
    int rb = t >> 3, cb = (t & 7) * 8;
    int tx = t & 15, ty = t >> 4;
    int gr = m0 + r;
    if (gr >= rows_out) gr = rows_out - 1;
    int jj = gr >> 4, bb = gr & 15;
    const float* arow = vin + (size_t)(32 * jj + 16 + bb) * HN;   // odd source row
    float acc[4][4] = {};
    for (int k0 = kbeg; k0 < kbeg + 256; k0 += 32) {
        float4 v0 = *(const float4*)(arow + k0 + c0);
        float4 v1 = *(const float4*)(arow + k0 + c0 + 4);
        if (vhoff) {
            float4 w0 = *(const float4*)(arow + vhoff + k0 + c0);
            float4 w1 = *(const float4*)(arow + vhoff + k0 + c0 + 4);
            v0.x += w0.x; v0.y += w0.y; v0.z += w0.z; v0.w += w0.w;
            v1.x += w1.x; v1.y += w1.y; v1.z += w1.z; v1.w += w1.w;
        }
        As[c0 + 0][r] = v0.x; As[c0 + 1][r] = v0.y; As[c0 + 2][r] = v0.z; As[c0 + 3][r] = v0.w;
        As[c0 + 4][r] = v1.x; As[c0 + 5][r] = v1.y; As[c0 + 6][r] = v1.z; As[c0 + 7][r] = v1.w;
        size_t boff = (size_t)(k0 + rb) * HN + n0 + cb;
        float4 u0 = *(const float4*)(b0 + boff);
        float4 u1 = *(const float4*)(b0 + boff + 4);
        if (b1) {
            float4 w0 = *(const float4*)(b1 + boff);
            float4 w1 = *(const float4*)(b1 + boff + 4);
            u0.x += w0.x; u0.y += w0.y; u0.z += w0.z; u0.w += w0.w;
            u1.x += w1.x; u1.y += w1.y; u1.z += w1.z; u1.w += w1.w;
        }
        *(float4*)&Bs[rb][cb]     = u0;
        *(float4*)&Bs[rb][cb + 4] = u1;
        __syncthreads();
#pragma unroll
        for (int kk = 0; kk < 32; kk++) {
            float4 a4 = *(const float4*)&As[kk][ty * 4];
            float4 b4 = *(const float4*)&Bs[kk][tx * 4];
            acc[0][0] += a4.x * b4.x; acc[0][1] += a4.x * b4.y; acc[0][2] += a4.x * b4.z; acc[0][3] += a4.x * b4.w;
            acc[1][0] += a4.y * b4.x; acc[1][1] += a4.y * b4.y; acc[1][2] += a4.y * b4.z; acc[1][3] += a4.y * b4.w;
            acc[2][0] += a4.z * b4.x; acc[2][1] += a4.z * b4.y; acc[2][2] += a4.z * b4.z; acc[2][3] += a4.z * b4.w;
            acc[3][0] += a4.w * b4.x; acc[3][1] += a4.w * b4.y; acc[3][2] += a4.w * b4.z; acc[3][3] += a4.w * b4.w;
        }
        __syncthreads();
    }
    float* cz = vout + (size_t)blockIdx.z * rows_out * HN;
#pragma unroll
    for (int i = 0; i < 4; i++) {
        int mo = m0 + ty * 4 + i;
        if (mo >= rows_out) break;
        int col = n0 + tx * 4;
        float4 v = {acc[i][0], acc[i][1], acc[i][2], acc[i][3]};
        if (blockIdx.z == 0) {                  // fold even term into half 0
            int je = mo >> 4, be = mo & 15;
            const float* ev = vin + (size_t)(32 * je + be) * HN + col;
            float4 e = *(const float4*)ev;
            if (vhoff) {
                float4 e2 = *(const float4*)(ev + vhoff);
                e.x += e2.x; e.y += e2.y; e.z += e2.z; e.w += e2.w;
            }
            v.x += e.x; v.y += e.y; v.z += e.z; v.w += e.w;
        }
        *(float4*)&cz[(size_t)mo * HN + col] = v;
    }
}

// --------------------------- z_last + layernorm -----------------------------
__global__ void k_ln(const float* __restrict__ x, const float* __restrict__ Wr,
                     const float* __restrict__ br, const float* __restrict__ lg,
                     const float* __restrict__ lb) {
    int b = blockIdx.x, j = threadIdx.x;    // 512 threads
    __shared__ float xs[LL];
    __shared__ float red[HN];
    if (j < LL) xs[j] = x[(size_t)(b * TT + (TT - 1)) * LL + j];
    __syncthreads();
    float hv = g_V2[(size_t)b * HN + j] + g_V2[16 * HN + (size_t)b * HN + j];
    float acc = br[j];
#pragma unroll 8
    for (int l = 0; l < LL; l++) acc += xs[l] * Wr[(size_t)l * HN + j];
    float z = hv + acc;
    red[j] = z; __syncthreads();
    for (int off = 256; off > 0; off >>= 1) {
        if (j < off) red[j] += red[j + off];
        __syncthreads();
    }
    float mu = red[0] / (float)HN;
    __syncthreads();
    float d = z - mu;
    red[j] = d * d; __syncthreads();
    for (int off = 256; off > 0; off >>= 1) {
        if (j < off) red[j] += red[j + off];
        __syncthreads();
    }
    float var = red[0] / (float)HN;
    g_zn[(size_t)b * HN + j] = d * rsqrtf(var + 1e-5f) * lg[j] + lb[j];
}

// --------------------------- MLP --------------------------------------------
__global__ void k_mlp1(const float* __restrict__ W1, const float* __restrict__ b1) {
    int b = blockIdx.x;
    int f = blockIdx.y * 128 + threadIdx.x;
    __shared__ float zs[HN];
    for (int i = threadIdx.x; i < HN; i += 128) zs[i] = g_zn[(size_t)b * HN + i];
    __syncthreads();
    float acc = b1[f];
#pragma unroll 8
    for (int j = 0; j < HN; j++) acc += zs[j] * W1[(size_t)j * FF + f];
    g_t1[(size_t)b * FF + f] = fmaxf(acc, 0.f);
}

__global__ void k_mlp2(const float* __restrict__ W2, const float* __restrict__ b2,
                       float* __restrict__ out) {
    int b = blockIdx.x;
    int j = blockIdx.y * 128 + threadIdx.x;
    __shared__ float ts[FF];
    for (int i = threadIdx.x; i < FF; i += 128) ts[i] = g_t1[(size_t)b * FF + i];
    __syncthreads();
    float acc = b2[j];
#pragma unroll 8
    for (int f = 0; f < FF; f++) acc += ts[f] * W2[(size_t)f * HN + j];
    out[(size_t)b * HN + j] = acc;
}

// --------------------------- launch -----------------------------------------
extern "C" void kernel_launch(void* const* d_in, const int* in_sizes, int n_in,
                              void* d_out, int out_size) {
    const float* x  = (const float*)d_in[0];
    const float* We = (const float*)d_in[1];
    const float* be = (const float*)d_in[2];
    const float* Wb = (const float*)d_in[3];
    const float* A  = (const float*)d_in[4];
    const float* Wr = (const float*)d_in[5];
    const float* br = (const float*)d_in[6];
    const float* lg = (const float*)d_in[7];
    const float* lb = (const float*)d_in[8];
    const float* W1 = (const float*)d_in[9];
    const float* b1 = (const float*)d_in[10];
    const float* W2 = (const float*)d_in[11];
    const float* b2 = (const float*)d_in[12];
    float* out = (float*)d_out;

    float* M[8];                       // M[l] = A^(2^l) halves, l=1..7
    // device-symbol addresses are valid to compute host-side via cudaGetSymbolAddress,
    // but simpler: pass offsets relative to a kernel-visible base. We instead use
    // cudaGetSymbolAddress once per launch call (cheap host work, graph-safe).
    static float* gM = nullptr; static float* gV1 = nullptr; static float* gV2 = nullptr;
    static float* gVa = nullptr;
    if (!gM)  cudaGetSymbolAddress((void**)&gM,  g_M);
    if (!gV1) cudaGetSymbolAddress((void**)&gV1, g_V1);
    if (!gV2) cudaGetSymbolAddress((void**)&gV2, g_V2);
    if (!gVa) cudaGetSymbolAddress((void**)&gVa, g_Va);
    for (int l = 1; l <= 7; l++) M[l] = gM + (size_t)(l - 1) * 2 * MSZ;

    k_init<<<258, 256>>>(We, be, Wb);
    k_bu<<<dim3(64, 8), 256>>>(x);

    // Level 0: M1 = A@A ; V1 = combine(V0, A)
    k_sq <<<dim3(8, 8, 2), 256>>>(A, nullptr, A, nullptr, M[1]);
    k_vec<<<dim3(32, 8, 2), 256>>>(gVa, 0, A, nullptr, gV1, 2048);
    // Levels 1..6: M_{l+1} = M_l^2 ; V_{l+1} = combine(V_l, M_l)
    k_sq <<<dim3(8, 8, 2), 256>>>(M[1], M[1] + MSZ, M[1], M[1] + MSZ, M[2]);
    k_vec<<<dim3(16, 8, 2), 256>>>(gV1, 2048 * HN, M[1], M[1] + MSZ, gV2, 1024);
    k_sq <<<dim3(8, 8, 2), 256>>>(M[2], M[2] + MSZ, M[2], M[2] + MSZ, M[3]);
    k_vec<<<dim3(8, 8, 2), 256>>>(gV2, 1024 * HN, M[2], M[2] + MSZ, gV1, 512);
    k_sq <<<dim3(8, 8, 2), 256>>>(M[3], M[3] + MSZ, M[3], M[3] + MSZ, M[4]);
    k_vec<<<dim3(4, 8, 2), 256>>>(gV1, 512 * HN, M[3], M[3] + MSZ, gV2, 256);
    k_sq <<<dim3(8, 8, 2), 256>>>(M[4], M[4] + MSZ, M[4], M[4] + MSZ, M[5]);
    k_vec<<<dim3(2, 8, 2), 256>>>(gV2, 256 * HN, M[4], M[4] + MSZ, gV1, 128);
    k_sq <<<dim3(8, 8, 2), 256>>>(M[5], M[5] + MSZ, M[5], M[5] + MSZ, M[6]);
    k_vec<<<dim3(1, 8, 2), 256>>>(gV1, 128 * HN, M[5], M[5] + MSZ, gV2, 64);
    k_sq <<<dim3(8, 8, 2), 256>>>(M[6], M[6] + MSZ, M[6], M[6] + MSZ, M[7]);
    k_vec<<<dim3(1, 8, 2), 256>>>(gV2, 64 * HN, M[6], M[6] + MSZ, gV1, 32);
    // Level 7: final combine -> 16 rows in gV2
    k_vec<<<dim3(1, 8, 2), 256>>>(gV1, 32 * HN, M[7], M[7] + MSZ, gV2, 16);

    k_ln<<<16, 512>>>(x, Wr, br, lg, lb);
    k_mlp1<<<dim3(16, 8), 128>>>(W1, b1);
    k_mlp2<<<dim3(16, 4), 128>>>(W2, b2, out);
}

// round 4
// speedup vs baseline: 1.6740x; 1.1888x over previous
#include <cuda_runtime.h>

// ---------------------------------------------------------------------------
// ReservoirLinearRNN — only the LAST timestep feeds the output.
// h_last = sum_{k<256} U_k A^k   (K=256 truncation, ||A^k||=0.95^k, err ~1e-6)
// Binary combine tree: V_{l+1}[j] = V_l[2j] + V_l[2j+1] @ M_l,  M_l = A^(2^l).
// R4: each level's squaring (M_{l+1} = M_l^2) and combine run in ONE launch,
// role-switched on blockIdx.x — the sq blocks fill the same wave as the vec
// blocks instead of a separate low-occupancy launch. 8 tree launches total.
// All GEMMs are K-split (z=2) writing partial halves; consumers sum halves.
// ---------------------------------------------------------------------------

namespace {
constexpr int HN  = 512;
constexpr int TT  = 2048;
constexpr int LL  = 128;
constexpr int MMc = 256;
constexpr int FF  = 1024;
constexpr int MSZ = HN * HN;      // 262144 floats
}

// Scratch (device globals only — no allocations)
__device__ float g_Weff[LL * HN];
__device__ float g_beff[HN];
__device__ float g_Va[4096 * HN];          // V0: rows m = k*16 + b (k = lag)
__device__ float g_V1[2 * 2048 * HN];      // ping
__device__ float g_V2[2 * 1024 * HN];      // pong
__device__ float g_M[7 * 2 * MSZ];         // M1..M7, each as 2 K-split halves
__device__ float g_zn[16 * HN];
__device__ float g_t1[16 * FF];

// --------------------------- init: Weff = We@Wb, beff = be@Wb ---------------
__global__ void k_init(const float* __restrict__ We, const float* __restrict__ be,
                       const float* __restrict__ Wb) {
    const int nWeff = LL * HN;
    const int total = nWeff + HN;
    for (int id = blockIdx.x * blockDim.x + threadIdx.x; id < total;
         id += gridDim.x * blockDim.x) {
        if (id < nWeff) {
            int l = id / HN, h = id % HN;
            float acc = 0.f;
            for (int m = 0; m < MMc; m++) acc += We[l * MMc + m] * Wb[m * HN + h];
            g_Weff[id] = acc;
        } else {
            int h = id - nWeff;
            float acc = 0.f;
            for (int m = 0; m < MMc; m++) acc += be[m] * Wb[m * HN + h];
            g_beff[h] = acc;
        }
    }
}

// --------------------------- V0 = Bu window GEMM -----------------------------
// row m = k*16 + b  ->  x[b, 2047-k, :] @ Weff + beff     (4096 x 512)
__global__ __launch_bounds__(256) void k_bu(const float* __restrict__ x) {
    __shared__ float As[32][64];
    __shared__ float Bs[32][64];
    int t  = threadIdx.x;
    int m0 = blockIdx.x * 64, n0 = blockIdx.y * 64;
    int r  = t >> 2, c0 = (t & 3) * 8;
    int m  = m0 + r;
    int k  = m >> 4, b = m & 15;
    int tt = (TT - 1) - k;
    const float* xrow = x + ((size_t)(b * TT + tt)) * LL;
    int rb = t >> 3, cb = (t & 7) * 8;
    int tx = t & 15, ty = t >> 4;
    float acc[4][4] = {};
    for (int k0 = 0; k0 < LL; k0 += 32) {
        float4 v0 = *(const float4*)(xrow + k0 + c0);
        float4 v1 = *(const float4*)(xrow + k0 + c0 + 4);
        As[c0 + 0][r] = v0.x; As[c0 + 1][r] = v0.y; As[c0 + 2][r] = v0.z; As[c0 + 3][r] = v0.w;
        As[c0 + 4][r] = v1.x; As[c0 + 5][r] = v1.y; As[c0 + 6][r] = v1.z; As[c0 + 7][r] = v1.w;
        const float* bp = g_Weff + (size_t)(k0 + rb) * HN + n0 + cb;
        *(float4*)&Bs[rb][cb]     = *(const float4*)bp;
        *(float4*)&Bs[rb][cb + 4] = *(const float4*)(bp + 4);
        __syncthreads();
#pragma unroll
        for (int kk = 0; kk < 32; kk++) {
            float4 a4 = *(const float4*)&As[kk][ty * 4];
            float4 b4 = *(const float4*)&Bs[kk][tx * 4];
            acc[0][0] += a4.x * b4.x; acc[0][1] += a4.x * b4.y; acc[0][2] += a4.x * b4.z; acc[0][3] += a4.x * b4.w;
            acc[1][0] += a4.y * b4.x; acc[1][1] += a4.y * b4.y; acc[1][2] += a4.y * b4.z; acc[1][3] += a4.y * b4.w;
            acc[2][0] += a4.z * b4.x; acc[2][1] += a4.z * b4.y; acc[2][2] += a4.z * b4.z; acc[2][3] += a4.z * b4.w;
            acc[3][0] += a4.w * b4.x; acc[3][1] += a4.w * b4.y; acc[3][2] += a4.w * b4.z; acc[3][3] += a4.w * b4.w;
        }
        __syncthreads();
    }
#pragma unroll
    for (int i = 0; i < 4; i++) {
        int col = n0 + tx * 4;
        float4 v;
        v.x = acc[i][0] + g_beff[col + 0];
        v.y = acc[i][1] + g_beff[col + 1];
        v.z = acc[i][2] + g_beff[col + 2];
        v.w = acc[i][3] + g_beff[col + 3];
        *(float4*)&g_Va[(size_t)(m0 + ty * 4 + i) * HN + col] = v;
    }
}

// --------------------------- fused level kernel ------------------------------
// blocks [0, nSq):        M_{l+1} partial = (m0+m1)[64-tile] @ (m0+m1), K-half z
// blocks [nSq, nSq+gx*16): V_{l+1} partial = V_l[odd] @ (m0+m1), + even fold
// nSq = 128 (8x8x2) or 0 for the last level.
__global__ __launch_bounds__(256) void k_lvl(const float* __restrict__ vin, int vhoff,
                                             const float* __restrict__ m0p,
                                             const float* __restrict__ m1p,
                                             float* __restrict__ vout, int rows_out,
                                             float* __restrict__ mout, int nSq) {
    __shared__ float As[32][64];
    __shared__ float Bs[32][64];
    int bid = blockIdx.x;
    bool isSq = bid < nSq;
    int gx = (rows_out + 63) >> 6;
    int bx, by, bz;
    if (isSq) {
        bx = bid & 7; by = (bid >> 3) & 7; bz = bid >> 6;
    } else {
        int vb = bid - nSq;
        bx = vb % gx; vb /= gx;
        by = vb & 7;  bz = vb >> 3;
    }
    int t  = threadIdx.x;
    int mt = bx * 64, n0 = by * 64;
    int kbeg = bz * 256;
    int r  = t >> 2, c0 = (t & 3) * 8;
    int rb = t >> 3, cb = (t & 7) * 8;
    int tx = t & 15, ty = t >> 4;

    const float* arow;
    const float* arow2 = nullptr;
    if (isSq) {
        arow = m0p + (size_t)(mt + r) * HN;
        if (m1p) arow2 = m1p + (size_t)(mt + r) * HN;
    } else {
        int gr = mt + r;
        if (gr >= rows_out) gr = rows_out - 1;
        int jj = gr >> 4, bb = gr & 15;
        arow = vin + (size_t)(32 * jj + 16 + bb) * HN;     // odd source row
        if (vhoff) arow2 = arow + vhoff;
    }

    float acc[4][4] = {};
    for (int k0 = kbeg; k0 < kbeg + 256; k0 += 32) {
        float4 v0 = *(const float4*)(arow + k0 + c0);
        float4 v1 = *(const float4*)(arow + k0 + c0 + 4);
        if (arow2) {
            float4 w0 = *(const float4*)(arow2 + k0 + c0);
            float4 w1 = *(const float4*)(arow2 + k0 + c0 + 4);
            v0.x += w0.x; v0.y += w0.y; v0.z += w0.z; v0.w += w0.w;
            v1.x += w1.x; v1.y += w1.y; v1.z += w1.z; v1.w += w1.w;
        }
        As[c0 + 0][r] = v0.x; As[c0 + 1][r] = v0.y; As[c0 + 2][r] = v0.z; As[c0 + 3][r] = v0.w;
        As[c0 + 4][r] = v1.x; As[c0 + 5][r] = v1.y; As[c0 + 6][r] = v1.z; As[c0 + 7][r] = v1.w;
        size_t boff = (size_t)(k0 + rb) * HN + n0 + cb;
        float4 u0 = *(const float4*)(m0p + boff);
        float4 u1 = *(const float4*)(m0p + boff + 4);
        if (m1p) {
            float4 w0 = *(const float4*)(m1p + boff);
            float4 w1 = *(const float4*)(m1p + boff + 4);
            u0.x += w0.x; u0.y += w0.y; u0.z += w0.z; u0.w += w0.w;
            u1.x += w1.x; u1.y += w1.y; u1.z += w1.z; u1.w += w1.w;
        }
        *(float4*)&Bs[rb][cb]     = u0;
        *(float4*)&Bs[rb][cb + 4] = u1;
        __syncthreads();
#pragma unroll
        for (int kk = 0; kk < 32; kk++) {
            float4 a4 = *(const float4*)&As[kk][ty * 4];
            float4 b4 = *(const float4*)&Bs[kk][tx * 4];
            acc[0][0] += a4.x * b4.x; acc[0][1] += a4.x * b4.y; acc[0][2] += a4.x * b4.z; acc[0][3] += a4.x * b4.w;
            acc[1][0] += a4.y * b4.x; acc[1][1] += a4.y * b4.y; acc[1][2] += a4.y * b4.z; acc[1][3] += a4.y * b4.w;
            acc[2][0] += a4.z * b4.x; acc[2][1] += a4.z * b4.y; acc[2][2] += a4.z * b4.z; acc[2][3] += a4.z * b4.w;
            acc[3][0] += a4.w * b4.x; acc[3][1] += a4.w * b4.y; acc[3][2] += a4.w * b4.z; acc[3][3] += a4.w * b4.w;
        }
        __syncthreads();
    }

    if (isSq) {
        float* cz = mout + (size_t)bz * MSZ;
#pragma unroll
        for (int i = 0; i < 4; i++) {
            float4 v = {acc[i][0], acc[i][1], acc[i][2], acc[i][3]};
            *(float4*)&cz[(size_t)(mt + ty * 4 + i) * HN + n0 + tx * 4] = v;
        }
    } else {
        float* cz = vout + (size_t)bz * rows_out * HN;
#pragma unroll
        for (int i = 0; i < 4; i++) {
            int mo = mt + ty * 4 + i;
            if (mo >= rows_out) break;
            int col = n0 + tx * 4;
            float4 v = {acc[i][0], acc[i][1], acc[i][2], acc[i][3]};
            if (bz == 0) {                  // fold even term into half 0
                int je = mo >> 4, be = mo & 15;
                const float* ev = vin + (size_t)(32 * je + be) * HN + col;
                float4 e = *(const float4*)ev;
                if (vhoff) {
                    float4 e2 = *(const float4*)(ev + vhoff);
                    e.x += e2.x; e.y += e2.y; e.z += e2.z; e.w += e2.w;
                }
                v.x += e.x; v.y += e.y; v.z += e.z; v.w += e.w;
            }
            *(float4*)&cz[(size_t)mo * HN + col] = v;
        }
    }
}

// --------------------------- z_last + layernorm -----------------------------
__global__ void k_ln(const float* __restrict__ x, const float* __restrict__ Wr,
                     const float* __restrict__ br, const float* __restrict__ lg,
                     const float* __restrict__ lb) {
    int b = blockIdx.x, j = threadIdx.x;    // 512 threads
    __shared__ float xs[LL];
    __shared__ float red[HN];
    if (j < LL) xs[j] = x[(size_t)(b * TT + (TT - 1)) * LL + j];
    __syncthreads();
    float hv = g_V2[(size_t)b * HN + j] + g_V2[16 * HN + (size_t)b * HN + j];
    float acc = br[j];
#pragma unroll 8
    for (int l = 0; l < LL; l++) acc += xs[l] * Wr[(size_t)l * HN + j];
    float z = hv + acc;
    red[j] = z; __syncthreads();
    for (int off = 256; off > 0; off >>= 1) {
        if (j < off) red[j] += red[j + off];
        __syncthreads();
    }
    float mu = red[0] / (float)HN;
    __syncthreads();
    float d = z - mu;
    red[j] = d * d; __syncthreads();
    for (int off = 256; off > 0; off >>= 1) {
        if (j < off) red[j] += red[j + off];
        __syncthreads();
    }
    float var = red[0] / (float)HN;
    g_zn[(size_t)b * HN + j] = d * rsqrtf(var + 1e-5f) * lg[j] + lb[j];
}

// --------------------------- MLP --------------------------------------------
__global__ void k_mlp1(const float* __restrict__ W1, const float* __restrict__ b1) {
    int b = blockIdx.x;
    int f = blockIdx.y * 128 + threadIdx.x;
    __shared__ float zs[HN];
    for (int i = threadIdx.x; i < HN; i += 128) zs[i] = g_zn[(size_t)b * HN + i];
    __syncthreads();
    float acc = b1[f];
#pragma unroll 8
    for (int j = 0; j < HN; j++) acc += zs[j] * W1[(size_t)j * FF + f];
    g_t1[(size_t)b * FF + f] = fmaxf(acc, 0.f);
}

__global__ void k_mlp2(const float* __restrict__ W2, const float* __restrict__ b2,
                       float* __restrict__ out) {
    int b = blockIdx.x;
    int j = blockIdx.y * 128 + threadIdx.x;
    __shared__ float ts[FF];
    for (int i = threadIdx.x; i < FF; i += 128) ts[i] = g_t1[(size_t)b * FF + i];
    __syncthreads();
    float acc = b2[j];
#pragma unroll 8
    for (int f = 0; f < FF; f++) acc += ts[f] * W2[(size_t)f * HN + j];
    out[(size_t)b * HN + j] = acc;
}

// --------------------------- launch -----------------------------------------
extern "C" void kernel_launch(void* const* d_in, const int* in_sizes, int n_in,
                              void* d_out, int out_size) {
    const float* x  = (const float*)d_in[0];
    const float* We = (const float*)d_in[1];
    const float* be = (const float*)d_in[2];
    const float* Wb = (const float*)d_in[3];
    const float* A  = (const float*)d_in[4];
    const float* Wr = (const float*)d_in[5];
    const float* br = (const float*)d_in[6];
    const float* lg = (const float*)d_in[7];
    const float* lb = (const float*)d_in[8];
    const float* W1 = (const float*)d_in[9];
    const float* b1 = (const float*)d_in[10];
    const float* W2 = (const float*)d_in[11];
    const float* b2 = (const float*)d_in[12];
    float* out = (float*)d_out;

    static float* gM = nullptr; static float* gV1 = nullptr; static float* gV2 = nullptr;
    static float* gVa = nullptr;
    if (!gM)  cudaGetSymbolAddress((void**)&gM,  g_M);
    if (!gV1) cudaGetSymbolAddress((void**)&gV1, g_V1);
    if (!gV2) cudaGetSymbolAddress((void**)&gV2, g_V2);
    if (!gVa) cudaGetSymbolAddress((void**)&gVa, g_Va);
    float* M[8];
    for (int l = 1; l <= 7; l++) M[l] = gM + (size_t)(l - 1) * 2 * MSZ;

    k_init<<<258, 256>>>(We, be, Wb);
    k_bu<<<dim3(64, 8), 256>>>(x);

    // Level l: fused [sq: M_{l+1} = M_l^2] + [vec: V_{l+1} = combine(V_l, M_l)]
    // grid = 128 sq blocks + ceil(rows_out/64)*16 vec blocks
    k_lvl<<<128 + 32 * 16, 256>>>(gVa, 0,          A,    nullptr,    gV1, 2048, M[1], 128);
    k_lvl<<<128 + 16 * 16, 256>>>(gV1, 2048 * HN,  M[1], M[1] + MSZ, gV2, 1024, M[2], 128);
    k_lvl<<<128 +  8 * 16, 256>>>(gV2, 1024 * HN,  M[2], M[2] + MSZ, gV1,  512, M[3], 128);
    k_lvl<<<128 +  4 * 16, 256>>>(gV1,  512 * HN,  M[3], M[3] + MSZ, gV2,  256, M[4], 128);
    k_lvl<<<128 +  2 * 16, 256>>>(gV2,  256 * HN,  M[4], M[4] + MSZ, gV1,  128, M[5], 128);
    k_lvl<<<128 +  1 * 16, 256>>>(gV1,  128 * HN,  M[5], M[5] + MSZ, gV2,   64, M[6], 128);
    k_lvl<<<128 +  1 * 16, 256>>>(gV2,   64 * HN,  M[6], M[6] + MSZ, gV1,   32, M[7], 128);
    k_lvl<<<        1 * 16, 256>>>(gV1,  32 * HN,  M[7], M[7] + MSZ, gV2,   16, nullptr, 0);

    k_ln<<<16, 512>>>(x, Wr, br, lg, lb);
    k_mlp1<<<dim3(16, 8), 128>>>(W1, b1);
    k_mlp2<<<dim3(16, 4), 128>>>(W2, b2, out);
}

// round 9
// speedup vs baseline: 1.6904x; 1.0098x over previous
#include <cuda_runtime.h>

// ---------------------------------------------------------------------------
// ReservoirLinearRNN — only the LAST timestep feeds the output.
// h_last = sum_{k<256} U_k A^k   (K=256 truncation, ||A^k||=0.95^k, err ~1e-6)
// Binary combine tree: V_{l+1}[j] = V_l[2j] + V_l[2j+1] @ M_l,  M_l = A^(2^l).
// Each level: fused [M_{l+1}=M_l^2] + [V_{l+1}=combine(V_l,M_l)] in ONE launch.
// R5..R9: double-buffered smem + register prefetch in k_lvl (1 barrier/tile).
// All GEMMs are K-split (z=2) writing partial halves; consumers sum halves.
// ---------------------------------------------------------------------------

namespace {
constexpr int HN  = 512;
constexpr int TT  = 2048;
constexpr int LL  = 128;
constexpr int MMc = 256;
constexpr int FF  = 1024;
constexpr int MSZ = HN * HN;      // 262144 floats
}

// Scratch (device globals only — no allocations)
__device__ float g_Weff[LL * HN];
__device__ float g_beff[HN];
__device__ float g_Va[4096 * HN];          // V0: rows m = k*16 + b (k = lag)
__device__ float g_V1[2 * 2048 * HN];      // ping
__device__ float g_V2[2 * 1024 * HN];      // pong
__device__ float g_M[7 * 2 * MSZ];         // M1..M7, each as 2 K-split halves
__device__ float g_zn[16 * HN];
__device__ float g_t1[16 * FF];

// --------------------------- init: Weff = We@Wb, beff = be@Wb ---------------
__global__ void k_init(const float* __restrict__ We, const float* __restrict__ be,
                       const float* __restrict__ Wb) {
    const int nWeff = LL * HN;
    const int total = nWeff + HN;
    for (int id = blockIdx.x * blockDim.x + threadIdx.x; id < total;
         id += gridDim.x * blockDim.x) {
        if (id < nWeff) {
            int l = id / HN, h = id % HN;
            float acc = 0.f;
            for (int m = 0; m < MMc; m++) acc += We[l * MMc + m] * Wb[m * HN + h];
            g_Weff[id] = acc;
        } else {
            int h = id - nWeff;
            float acc = 0.f;
            for (int m = 0; m < MMc; m++) acc += be[m] * Wb[m * HN + h];
            g_beff[h] = acc;
        }
    }
}

// --------------------------- V0 = Bu window GEMM -----------------------------
// row m = k*16 + b  ->  x[b, 2047-k, :] @ Weff + beff     (4096 x 512)
__global__ __launch_bounds__(256) void k_bu(const float* __restrict__ x) {
    __shared__ float As[32][64];
    __shared__ float Bs[32][64];
    int t  = threadIdx.x;
    int m0 = blockIdx.x * 64, n0 = blockIdx.y * 64;
    int r  = t >> 2, c0 = (t & 3) * 8;
    int m  = m0 + r;
    int k  = m >> 4, b = m & 15;
    int tt = (TT - 1) - k;
    const float* xrow = x + ((size_t)(b * TT + tt)) * LL;
    int rb = t >> 3, cb = (t & 7) * 8;
    int tx = t & 15, ty = t >> 4;
    float acc[4][4] = {};
    for (int k0 = 0; k0 < LL; k0 += 32) {
        float4 v0 = *(const float4*)(xrow + k0 + c0);
        float4 v1 = *(const float4*)(xrow + k0 + c0 + 4);
        As[c0 + 0][r] = v0.x; As[c0 + 1][r] = v0.y; As[c0 + 2][r] = v0.z; As[c0 + 3][r] = v0.w;
        As[c0 + 4][r] = v1.x; As[c0 + 5][r] = v1.y; As[c0 + 6][r] = v1.z; As[c0 + 7][r] = v1.w;
        const float* bp = g_Weff + (size_t)(k0 + rb) * HN + n0 + cb;
        *(float4*)&Bs[rb][cb]     = *(const float4*)bp;
        *(float4*)&Bs[rb][cb + 4] = *(const float4*)(bp + 4);
        __syncthreads();
#pragma unroll
        for (int kk = 0; kk < 32; kk++) {
            float4 a4 = *(const float4*)&As[kk][ty * 4];
            float4 b4 = *(const float4*)&Bs[kk][tx * 4];
            acc[0][0] += a4.x * b4.x; acc[0][1] += a4.x * b4.y; acc[0][2] += a4.x * b4.z; acc[0][3] += a4.x * b4.w;
            acc[1][0] += a4.y * b4.x; acc[1][1] += a4.y * b4.y; acc[1][2] += a4.y * b4.z; acc[1][3] += a4.y * b4.w;
            acc[2][0] += a4.z * b4.x; acc[2][1] += a4.z * b4.y; acc[2][2] += a4.z * b4.z; acc[2][3] += a4.z * b4.w;
            acc[3][0] += a4.w * b4.x; acc[3][1] += a4.w * b4.y; acc[3][2] += a4.w * b4.z; acc[3][3] += a4.w * b4.w;
        }
        __syncthreads();
    }
#pragma unroll
    for (int i = 0; i < 4; i++) {
        int col = n0 + tx * 4;
        float4 v;
        v.x = acc[i][0] + g_beff[col + 0];
        v.y = acc[i][1] + g_beff[col + 1];
        v.z = acc[i][2] + g_beff[col + 2];
        v.w = acc[i][3] + g_beff[col + 3];
        *(float4*)&g_Va[(size_t)(m0 + ty * 4 + i) * HN + col] = v;
    }
}

// --------------------------- fused level kernel ------------------------------
// blocks [0, nSq):        M_{l+1} partial = (m0+m1)[64-tile] @ (m0+m1), K-half z
// blocks [nSq, nSq+gx*16): V_{l+1} partial = V_l[odd] @ (m0+m1), + even fold
// Double-buffered smem, register prefetch, one barrier per K-tile.
__global__ __launch_bounds__(256) void k_lvl(const float* __restrict__ vin, int vhoff,
                                             const float* __restrict__ m0p,
                                             const float* __restrict__ m1p,
                                             float* __restrict__ vout, int rows_out,
                                             float* __restrict__ mout, int nSq) {
    __shared__ float As[2][32][64];
    __shared__ float Bs[2][32][64];
    int bid = blockIdx.x;
    bool isSq = bid < nSq;
    int gx = (rows_out + 63) >> 6;
    int bx, by, bz;
    if (isSq) {
        bx = bid & 7; by = (bid >> 3) & 7; bz = bid >> 6;
    } else {
        int vb = bid - nSq;
        bx = vb % gx; vb /= gx;
        by = vb & 7;  bz = vb >> 3;
    }
    int t  = threadIdx.x;
    int mt = bx * 64, n0 = by * 64;
    int kbeg = bz * 256;
    int r  = t >> 2, c0 = (t & 3) * 8;
    int rb = t >> 3, cb = (t & 7) * 8;
    int tx = t & 15, ty = t >> 4;

    const float* arow;
    const float* arow2 = nullptr;
    if (isSq) {
        arow = m0p + (size_t)(mt + r) * HN;
        if (m1p) arow2 = m1p + (size_t)(mt + r) * HN;
    } else {
        int gr = mt + r;
        if (gr >= rows_out) gr = rows_out - 1;
        int jj = gr >> 4, bb = gr & 15;
        arow = vin + (size_t)(32 * jj + 16 + bb) * HN;     // odd source row
        if (vhoff) arow2 = arow + vhoff;
    }

    // prefetch helpers (A: 8 floats along k at row r; B: 8 floats along n at k-row rb)
    float4 pa0, pa1, pb0, pb1;
    auto loadA = [&](int k0, float4& va0, float4& va1) {
        va0 = *(const float4*)(arow + k0 + c0);
        va1 = *(const float4*)(arow + k0 + c0 + 4);
        if (arow2) {
            float4 w0 = *(const float4*)(arow2 + k0 + c0);
            float4 w1 = *(const float4*)(arow2 + k0 + c0 + 4);
            va0.x += w0.x; va0.y += w0.y; va0.z += w0.z; va0.w += w0.w;
            va1.x += w1.x; va1.y += w1.y; va1.z += w1.z; va1.w += w1.w;
        }
    };
    auto loadB = [&](int k0, float4& vb0, float4& vb1) {
        size_t boff = (size_t)(k0 + rb) * HN + n0 + cb;
        vb0 = *(const float4*)(m0p + boff);
        vb1 = *(const float4*)(m0p + boff + 4);
        if (m1p) {
            float4 w0 = *(const float4*)(m1p + boff);
            float4 w1 = *(const float4*)(m1p + boff + 4);
            vb0.x += w0.x; vb0.y += w0.y; vb0.z += w0.z; vb0.w += w0.w;
            vb1.x += w1.x; vb1.y += w1.y; vb1.z += w1.z; vb1.w += w1.w;
        }
    };
    auto stash = [&](int buf, const float4& va0, const float4& va1,
                     const float4& vb0, const float4& vb1) {
        As[buf][c0 + 0][r] = va0.x; As[buf][c0 + 1][r] = va0.y;
        As[buf][c0 + 2][r] = va0.z; As[buf][c0 + 3][r] = va0.w;
        As[buf][c0 + 4][r] = va1.x; As[buf][c0 + 5][r] = va1.y;
        As[buf][c0 + 6][r] = va1.z; As[buf][c0 + 7][r] = va1.w;
        *(float4*)&Bs[buf][rb][cb]     = vb0;
        *(float4*)&Bs[buf][rb][cb + 4] = vb1;
    };

    float acc[4][4] = {};
    loadA(kbeg, pa0, pa1);
    loadB(kbeg, pb0, pb1);
    stash(0, pa0, pa1, pb0, pb1);
    __syncthreads();

    int buf = 0;
    const int kend = kbeg + 256;
#pragma unroll 1
    for (int k0 = kbeg; k0 < kend; k0 += 32) {
        bool has = (k0 + 32) < kend;
        if (has) {
            loadA(k0 + 32, pa0, pa1);
            loadB(k0 + 32, pb0, pb1);
        }
#pragma unroll
        for (int kk = 0; kk < 32; kk++) {
            float4 a4 = *(const float4*)&As[buf][kk][ty * 4];
            float4 b4 = *(const float4*)&Bs[buf][kk][tx * 4];
            acc[0][0] += a4.x * b4.x; acc[0][1] += a4.x * b4.y; acc[0][2] += a4.x * b4.z; acc[0][3] += a4.x * b4.w;
            acc[1][0] += a4.y * b4.x; acc[1][1] += a4.y * b4.y; acc[1][2] += a4.y * b4.z; acc[1][3] += a4.y * b4.w;
            acc[2][0] += a4.z * b4.x; acc[2][1] += a4.z * b4.y; acc[2][2] += a4.z * b4.z; acc[2][3] += a4.z * b4.w;
            acc[3][0] += a4.w * b4.x; acc[3][1] += a4.w * b4.y; acc[3][2] += a4.w * b4.z; acc[3][3] += a4.w * b4.w;
        }
        if (has) stash(buf ^ 1, pa0, pa1, pb0, pb1);
        __syncthreads();
        buf ^= 1;
    }

    if (isSq) {
        float* cz = mout + (size_t)bz * MSZ;
#pragma unroll
        for (int i = 0; i < 4; i++) {
            float4 v = {acc[i][0], acc[i][1], acc[i][2], acc[i][3]};
            *(float4*)&cz[(size_t)(mt + ty * 4 + i) * HN + n0 + tx * 4] = v;
        }
    } else {
        float* cz = vout + (size_t)bz * rows_out * HN;
#pragma unroll
        for (int i = 0; i < 4; i++) {
            int mo = mt + ty * 4 + i;
            if (mo >= rows_out) break;
            int col = n0 + tx * 4;
            float4 v = {acc[i][0], acc[i][1], acc[i][2], acc[i][3]};
            if (bz == 0) {                  // fold even term into half 0
                int je = mo >> 4, be = mo & 15;
                const float* ev = vin + (size_t)(32 * je + be) * HN + col;
                float4 e = *(const float4*)ev;
                if (vhoff) {
                    float4 e2 = *(const float4*)(ev + vhoff);
                    e.x += e2.x; e.y += e2.y; e.z += e2.z; e.w += e2.w;
                }
                v.x += e.x; v.y += e.y; v.z += e.z; v.w += e.w;
            }
            *(float4*)&cz[(size_t)mo * HN + col] = v;
        }
    }
}

// --------------------------- z_last + layernorm -----------------------------
__global__ void k_ln(const float* __restrict__ x, const float* __restrict__ Wr,
                     const float* __restrict__ br, const float* __restrict__ lg,
                     const float* __restrict__ lb) {
    int b = blockIdx.x, j = threadIdx.x;    // 512 threads
    __shared__ float xs[LL];
    __shared__ float red[HN];
    if (j < LL) xs[j] = x[(size_t)(b * TT + (TT - 1)) * LL + j];
    __syncthreads();
    float hv = g_V2[(size_t)b * HN + j] + g_V2[16 * HN + (size_t)b * HN + j];
    float acc = br[j];
#pragma unroll 8
    for (int l = 0; l < LL; l++) acc += xs[l] * Wr[(size_t)l * HN + j];
    float z = hv + acc;
    red[j] = z; __syncthreads();
    for (int off = 256; off > 0; off >>= 1) {
        if (j < off) red[j] += red[j + off];
        __syncthreads();
    }
    float mu = red[0] / (float)HN;
    __syncthreads();
    float d = z - mu;
    red[j] = d * d; __syncthreads();
    for (int off = 256; off > 0; off >>= 1) {
        if (j < off) red[j] += red[j + off];
        __syncthreads();
    }
    float var = red[0] / (float)HN;
    g_zn[(size_t)b * HN + j] = d * rsqrtf(var + 1e-5f) * lg[j] + lb[j];
}

// --------------------------- MLP --------------------------------------------
__global__ void k_mlp1(const float* __restrict__ W1, const float* __restrict__ b1) {
    int b = blockIdx.x;
    int f = blockIdx.y * 128 + threadIdx.x;
    __shared__ float zs[HN];
    for (int i = threadIdx.x; i < HN; i += 128) zs[i] = g_zn[(size_t)b * HN + i];
    __syncthreads();
    float acc = b1[f];
#pragma unroll 8
    for (int j = 0; j < HN; j++) acc += zs[j] * W1[(size_t)j * FF + f];
    g_t1[(size_t)b * FF + f] = fmaxf(acc, 0.f);
}

__global__ void k_mlp2(const float* __restrict__ W2, const float* __restrict__ b2,
                       float* __restrict__ out) {
    int b = blockIdx.x;
    int j = blockIdx.y * 128 + threadIdx.x;
    __shared__ float ts[FF];
    for (int i = threadIdx.x; i < FF; i += 128) ts[i] = g_t1[(size_t)b * FF + i];
    __syncthreads();
    float acc = b2[j];
#pragma unroll 8
    for (int f = 0; f < FF; f++) acc += ts[f] * W2[(size_t)f * HN + j];
    out[(size_t)b * HN + j] = acc;
}

// --------------------------- launch -----------------------------------------
extern "C" void kernel_launch(void* const* d_in, const int* in_sizes, int n_in,
                              void* d_out, int out_size) {
    const float* x  = (const float*)d_in[0];
    const float* We = (const float*)d_in[1];
    const float* be = (const float*)d_in[2];
    const float* Wb = (const float*)d_in[3];
    const float* A  = (const float*)d_in[4];
    const float* Wr = (const float*)d_in[5];
    const float* br = (const float*)d_in[6];
    const float* lg = (const float*)d_in[7];
    const float* lb = (const float*)d_in[8];
    const float* W1 = (const float*)d_in[9];
    const float* b1 = (const float*)d_in[10];
    const float* W2 = (const float*)d_in[11];
    const float* b2 = (const float*)d_in[12];
    float* out = (float*)d_out;

    static float* gM = nullptr; static float* gV1 = nullptr; static float* gV2 = nullptr;
    static float* gVa = nullptr;
    if (!gM)  cudaGetSymbolAddress((void**)&gM,  g_M);
    if (!gV1) cudaGetSymbolAddress((void**)&gV1, g_V1);
    if (!gV2) cudaGetSymbolAddress((void**)&gV2, g_V2);
    if (!gVa) cudaGetSymbolAddress((void**)&gVa, g_Va);
    float* M[8];
    for (int l = 1; l <= 7; l++) M[l] = gM + (size_t)(l - 1) * 2 * MSZ;

    k_init<<<258, 256>>>(We, be, Wb);
    k_bu<<<dim3(64, 8), 256>>>(x);

    // Level l: fused [sq: M_{l+1} = M_l^2] + [vec: V_{l+1} = combine(V_l, M_l)]
    // grid = 128 sq blocks + ceil(rows_out/64)*16 vec blocks
    k_lvl<<<128 + 32 * 16, 256>>>(gVa, 0,          A,    nullptr,    gV1, 2048, M[1], 128);
    k_lvl<<<128 + 16 * 16, 256>>>(gV1, 2048 * HN,  M[1], M[1] + MSZ, gV2, 1024, M[2], 128);
    k_lvl<<<128 +  8 * 16, 256>>>(gV2, 1024 * HN,  M[2], M[2] + MSZ, gV1,  512, M[3], 128);
    k_lvl<<<128 +  4 * 16, 256>>>(gV1,  512 * HN,  M[3], M[3] + MSZ, gV2,  256, M[4], 128);
    k_lvl<<<128 +  2 * 16, 256>>>(gV2,  256 * HN,  M[4], M[4] + MSZ, gV1,  128, M[5], 128);
    k_lvl<<<128 +  1 * 16, 256>>>(gV1,  128 * HN,  M[5], M[5] + MSZ, gV2,   64, M[6], 128);
    k_lvl<<<128 +  1 * 16, 256>>>(gV2,   64 * HN,  M[6], M[6] + MSZ, gV1,   32, M[7], 128);
    k_lvl<<<        1 * 16, 256>>>(gV1,  32 * HN,  M[7], M[7] + MSZ, gV2,   16, nullptr, 0);

    k_ln<<<16, 512>>>(x, Wr, br, lg, lb);
    k_mlp1<<<dim3(16, 8), 128>>>(W1, b1);
    k_mlp2<<<dim3(16, 4), 128>>>(W2, b2, out);
}